// round 13
// baseline (speedup 1.0000x reference)
#include <cuda_runtime.h>
#include <cuda_bf16.h>
#include <cstdint>

// Residual quantization, N=65536, D=512, K=1024, L=4.  (R12 + lean epilogues)
// Phase 1: bf16 mma.sync (m16n8k16), ldmatrix feed, per-cq distance-2 cp.async
//          pipeline (exact R6 schedule).
// Phase 2: margin-collect -> exact fp32 rescore; cnt==1 short-circuits (the sole
//          within-margin candidate IS the argmin); list overflow -> full scan.
// Update:  fused, row-per-quad layout (no shuffles): v = r - e (exact fp32) feeds
//          g_res, bf16 A-smem, and R1-order rsq partials. quant written once.

#define NROWS 65536
#define DDIM  512
#define KCB   1024
#define LLEV  4
#define ROWS  64
#define TPB   256
#define ASTR  1040        // A row stride bytes (1024 data + 16 pad, conflict-free)
#define MARGIN 0.02f
#define MAXC  16

#define SM_A      0        // 64*1040      = 66560
#define SM_B      66560    // 2*16384      -> 99328 (swizzled, no pad)
#define SM_CSQ    99328    // 4096         -> 103424
#define SM_RSQ    103424   // 256          -> 103680
#define SM_RUNMIN 103680   // 256          -> 103936
#define SM_CCNT   103936   // 256          -> 104192
#define SM_CLIST  104192   // 64*16*4=4096 -> 108288 (PART aliases first 1KB)
#define SM_ROWKEY 108288   // 512          -> 108800
#define SM_TOTAL  108800

__device__ float g_csq[LLEV * KCB];
__device__ float g_res[(size_t)NROWS * DDIM];
__device__ __align__(16) __nv_bfloat16 g_cb16[(size_t)LLEV * KCB * DDIM];

__device__ __forceinline__ uint32_t smem_u32(const void* p) {
    uint32_t a;
    asm("{ .reg .u64 t; cvta.to.shared.u64 t, %1; cvt.u32.u64 %0, t; }" : "=r"(a) : "l"(p));
    return a;
}
__device__ __forceinline__ void cpa16(uint32_t dst, const void* src) {
    asm volatile("cp.async.cg.shared.global [%0], [%1], 16;" :: "r"(dst), "l"(src));
}
__device__ __forceinline__ void cpa_commit() {
    asm volatile("cp.async.commit_group;" ::: "memory");
}
__device__ __forceinline__ void ldm_x4(uint32_t addr, uint32_t* r) {
    asm volatile("ldmatrix.sync.aligned.m8n8.x4.shared.b16 {%0,%1,%2,%3}, [%4];"
                 : "=r"(r[0]), "=r"(r[1]), "=r"(r[2]), "=r"(r[3]) : "r"(addr));
}

#define MMA16816(c, a0, a1, a2, a3, b0, b1)                                     \
    asm volatile(                                                               \
        "mma.sync.aligned.m16n8k16.row.col.f32.bf16.bf16.f32 "                  \
        "{%0,%1,%2,%3}, {%4,%5,%6,%7}, {%8,%9}, {%0,%1,%2,%3};"                 \
        : "+f"((c)[0]), "+f"((c)[1]), "+f"((c)[2]), "+f"((c)[3])                \
        : "r"(a0), "r"(a1), "r"(a2), "r"(a3), "r"(b0), "r"(b1))

__device__ __forceinline__ float dot512(const float* cbrow, int lane,
                                        float4 rv0, float4 rv1, float4 rv2, float4 rv3) {
    const float4* cp = (const float4*)cbrow + lane * 4;
    float4 c0 = cp[0], c1 = cp[1], c2 = cp[2], c3 = cp[3];
    float s = 0.f;
    s = fmaf(rv0.x, c0.x, s); s = fmaf(rv0.y, c0.y, s);
    s = fmaf(rv0.z, c0.z, s); s = fmaf(rv0.w, c0.w, s);
    s = fmaf(rv1.x, c1.x, s); s = fmaf(rv1.y, c1.y, s);
    s = fmaf(rv1.z, c1.z, s); s = fmaf(rv1.w, c1.w, s);
    s = fmaf(rv2.x, c2.x, s); s = fmaf(rv2.y, c2.y, s);
    s = fmaf(rv2.z, c2.z, s); s = fmaf(rv2.w, c2.w, s);
    s = fmaf(rv3.x, c3.x, s); s = fmaf(rv3.y, c3.y, s);
    s = fmaf(rv3.z, c3.z, s); s = fmaf(rv3.w, c3.w, s);
    #pragma unroll
    for (int o = 16; o; o >>= 1) s += __shfl_xor_sync(0xffffffffu, s, o);
    return s;
}

// ---------------------------------------------------------------------------
// prep: exact fp32 csq (R1 order) + bf16-rounded codebook copy
// ---------------------------------------------------------------------------
__global__ void prep_kernel(const float* __restrict__ cb) {
    int warp = (blockIdx.x * blockDim.x + threadIdx.x) >> 5;
    int lane = threadIdx.x & 31;
    if (warp >= LLEV * KCB) return;
    const float4* p = (const float4*)(cb + (size_t)warp * DDIM);
    __nv_bfloat162* o = (__nv_bfloat162*)(g_cb16 + (size_t)warp * DDIM);
    float s = 0.f;
    #pragma unroll
    for (int i = lane; i < DDIM / 4; i += 32) {
        float4 v = p[i];
        s = fmaf(v.x, v.x, s);
        s = fmaf(v.y, v.y, s);
        s = fmaf(v.z, v.z, s);
        s = fmaf(v.w, v.w, s);
        o[2 * i]     = __floats2bfloat162_rn(v.x, v.y);
        o[2 * i + 1] = __floats2bfloat162_rn(v.z, v.w);
    }
    #pragma unroll
    for (int q = 16; q; q >>= 1) s += __shfl_down_sync(0xffffffffu, s, q);
    if (lane == 0) g_csq[warp] = s;
}

// ---------------------------------------------------------------------------
// B tile fill: 256 codes x 32 d (64 bytes), XOR-swizzled 16B segments
// ---------------------------------------------------------------------------
__device__ __forceinline__ void bload(uint32_t sma, const __nv_bfloat16* cb16l,
                                      int buf, int cq, int dc, int t) {
    uint32_t dst0 = sma + SM_B + buf * 16384;
    const char* src0 = (const char*)cb16l + (size_t)cq * 256 * 1024 + dc * 64;
    #pragma unroll
    for (int i = 0; i < 4; ++i) {
        int e = t + i * TPB;            // 0..1023
        int code = e >> 2, seg = e & 3;
        uint32_t off = (uint32_t)(code * 64) + (uint32_t)((seg ^ ((code >> 1) & 3)) << 4);
        cpa16(dst0 + off, src0 + (size_t)code * 1024 + seg * 16);
    }
}

// ---------------------------------------------------------------------------
__global__ void __launch_bounds__(TPB, 2)
rq_kernel(const float* __restrict__ inp, const float* __restrict__ cb,
          float* __restrict__ outq, float* __restrict__ outc, int write_codes)
{
    extern __shared__ char smb[];
    float* csq_s = (float*)(smb + SM_CSQ);
    float* rsq_s = (float*)(smb + SM_RSQ);
    float* part  = (float*)(smb + SM_CLIST);   // aliased: dead before clist is used
    uint32_t* runmin = (uint32_t*)(smb + SM_RUNMIN);
    uint32_t* ccnt   = (uint32_t*)(smb + SM_CCNT);
    int* clist       = (int*)(smb + SM_CLIST);
    unsigned long long* rowkey = (unsigned long long*)(smb + SM_ROWKEY);

    const int t = threadIdx.x, lane = t & 31, wid = t >> 5;
    const int gid = lane >> 2, tig = lane & 3;
    const int wrow = wid & 1, wcol = wid >> 1;
    const int n0 = blockIdx.x * ROWS;
    const uint32_t sma = smem_u32(smb);
    const int l16 = lane & 15, lhi4 = lane >> 4;
    const int urow = t >> 2, useg = t & 3;     // update/convert layout

    for (int l = 0; l < LLEV; ++l) {
        const float* rptr = (l ? g_res : inp) + (size_t)n0 * DDIM;
        const float* cbl = cb + (size_t)l * KCB * DDIM;
        const __nv_bfloat16* cb16l = g_cb16 + (size_t)l * KCB * DDIM;

        for (int i = t; i < KCB; i += TPB) csq_s[i] = g_csq[l * KCB + i];
        if (t < ROWS) { runmin[t] = 0x7f800000u; ccnt[t] = 0u; }

        if (l == 0) {
            // level 0 only: convert input -> bf16 A smem; exact rsq partials
            const float4* rp = (const float4*)(rptr + (size_t)urow * DDIM + useg * 128);
            char* ap = smb + SM_A + urow * ASTR + useg * 256;
            float s = 0.f;
            #pragma unroll
            for (int m = 0; m < 16; ++m) {
                float4 v0 = rp[2 * m], v1 = rp[2 * m + 1];
                s = fmaf(v0.x, v0.x, s); s = fmaf(v0.y, v0.y, s);
                s = fmaf(v0.z, v0.z, s); s = fmaf(v0.w, v0.w, s);
                s = fmaf(v1.x, v1.x, s); s = fmaf(v1.y, v1.y, s);
                s = fmaf(v1.z, v1.z, s); s = fmaf(v1.w, v1.w, s);
                __nv_bfloat162 b0 = __floats2bfloat162_rn(v0.x, v0.y);
                __nv_bfloat162 b1 = __floats2bfloat162_rn(v0.z, v0.w);
                __nv_bfloat162 b2 = __floats2bfloat162_rn(v1.x, v1.y);
                __nv_bfloat162 b3 = __floats2bfloat162_rn(v1.z, v1.w);
                uint4 u;
                u.x = *(uint32_t*)&b0; u.y = *(uint32_t*)&b1;
                u.z = *(uint32_t*)&b2; u.w = *(uint32_t*)&b3;
                *(uint4*)(ap + m * 16) = u;
            }
            part[useg * ROWS + urow] = s;
            __syncthreads();
            if (t < ROWS)
                rsq_s[t] = ((part[t] + part[ROWS + t]) + part[2 * ROWS + t])
                           + part[3 * ROWS + t];
        }
        __syncthreads();

        // ---- phase 1: approximate GEMM (exact R6 schedule) + margin collection ----
        for (int cq = 0; cq < 4; ++cq) {
            float acc[2][8][4];
            #pragma unroll
            for (int i = 0; i < 2; ++i)
                #pragma unroll
                for (int j = 0; j < 8; ++j)
                    #pragma unroll
                    for (int k = 0; k < 4; ++k) acc[i][j][k] = 0.f;

            bload(sma, cb16l, 0, cq, 0, t); cpa_commit();
            bload(sma, cb16l, 1, cq, 1, t); cpa_commit();

            const uint32_t aaddr0 = sma + SM_A + (wrow * 32 + l16) * ASTR + (lhi4 << 4);
            for (int dc = 0; dc < 16; ++dc) {
                asm volatile("cp.async.wait_group 1;" ::: "memory");
                __syncthreads();
                const uint32_t bbase = sma + SM_B + (dc & 1) * 16384;
                #pragma unroll
                for (int ks = 0; ks < 2; ++ks) {
                    uint32_t a0[4], a1[4];
                    ldm_x4(aaddr0 + dc * 64 + ks * 32, a0);
                    ldm_x4(aaddr0 + 16 * ASTR + dc * 64 + ks * 32, a1);
                    const int bseg = ks * 2 + lhi4;
                    #pragma unroll
                    for (int j2 = 0; j2 < 4; ++j2) {
                        int brow = wcol * 64 + j2 * 16 + l16;
                        uint32_t baddr = bbase + brow * 64
                                         + ((bseg ^ ((brow >> 1) & 3)) << 4);
                        uint32_t b[4];
                        ldm_x4(baddr, b);
                        MMA16816(acc[0][2 * j2],     a0[0], a0[1], a0[2], a0[3], b[0], b[2]);
                        MMA16816(acc[0][2 * j2 + 1], a0[0], a0[1], a0[2], a0[3], b[1], b[3]);
                        MMA16816(acc[1][2 * j2],     a1[0], a1[1], a1[2], a1[3], b[0], b[2]);
                        MMA16816(acc[1][2 * j2 + 1], a1[0], a1[1], a1[2], a1[3], b[1], b[3]);
                    }
                }
                __syncthreads();
                if (dc + 2 < 16) bload(sma, cb16l, dc & 1, cq, dc + 2, t);
                cpa_commit();
            }

            // scores in place of acc; update running row minima
            const int cqbase = cq * 256;
            float rsqv[2][2], smin[2][2];
            #pragma unroll
            for (int i = 0; i < 2; ++i)
                #pragma unroll
                for (int h = 0; h < 2; ++h) {
                    rsqv[i][h] = rsq_s[wrow * 32 + i * 16 + gid + h * 8];
                    smin[i][h] = __int_as_float(0x7f800000);
                }
            #pragma unroll
            for (int i = 0; i < 2; ++i)
                #pragma unroll
                for (int j = 0; j < 8; ++j) {
                    int code0 = cqbase + wcol * 64 + j * 8 + tig * 2;
                    float cq0 = csq_s[code0], cq1 = csq_s[code0 + 1];
                    float s0 = (rsqv[i][0] + cq0) - 2.0f * acc[i][j][0];
                    float s1 = (rsqv[i][0] + cq1) - 2.0f * acc[i][j][1];
                    float s2 = (rsqv[i][1] + cq0) - 2.0f * acc[i][j][2];
                    float s3 = (rsqv[i][1] + cq1) - 2.0f * acc[i][j][3];
                    acc[i][j][0] = s0; acc[i][j][1] = s1;
                    acc[i][j][2] = s2; acc[i][j][3] = s3;
                    smin[i][0] = fminf(smin[i][0], fminf(s0, s1));
                    smin[i][1] = fminf(smin[i][1], fminf(s2, s3));
                }
            #pragma unroll
            for (int i = 0; i < 2; ++i)
                #pragma unroll
                for (int h = 0; h < 2; ++h)
                    atomicMin(&runmin[wrow * 32 + i * 16 + gid + h * 8],
                              __float_as_uint(smin[i][h]));
            __syncthreads();
            // collect candidates within margin of running min
            #pragma unroll
            for (int i = 0; i < 2; ++i) {
                float thr0 = __uint_as_float(runmin[wrow * 32 + i * 16 + gid]) + MARGIN;
                float thr1 = __uint_as_float(runmin[wrow * 32 + i * 16 + gid + 8]) + MARGIN;
                int row0 = wrow * 32 + i * 16 + gid, row1 = row0 + 8;
                #pragma unroll
                for (int j = 0; j < 8; ++j) {
                    int code0 = cqbase + wcol * 64 + j * 8 + tig * 2;
                    if (acc[i][j][0] < thr0) {
                        uint32_t sl = atomicAdd(&ccnt[row0], 1u);
                        if (sl < MAXC) clist[row0 * MAXC + sl] = code0;
                    }
                    if (acc[i][j][1] < thr0) {
                        uint32_t sl = atomicAdd(&ccnt[row0], 1u);
                        if (sl < MAXC) clist[row0 * MAXC + sl] = code0 + 1;
                    }
                    if (acc[i][j][2] < thr1) {
                        uint32_t sl = atomicAdd(&ccnt[row1], 1u);
                        if (sl < MAXC) clist[row1 * MAXC + sl] = code0;
                    }
                    if (acc[i][j][3] < thr1) {
                        uint32_t sl = atomicAdd(&ccnt[row1], 1u);
                        if (sl < MAXC) clist[row1 * MAXC + sl] = code0 + 1;
                    }
                }
            }
            // trailing sync removed: next dc-loop's top barrier provides ordering
        }
        __syncthreads();   // clist/ccnt visible to phase 2

        // ---- phase 2: cnt==1 shortcut; else exact fp32 rescore / full scan ----
        for (int r8 = 0; r8 < 8; ++r8) {
            int row = wid * 8 + r8;
            int cnt = (int)ccnt[row];
            if (cnt == 1) {
                // sole within-margin candidate IS the argmin (min always collected)
                if (lane == 0)
                    rowkey[row] = (unsigned long long)(unsigned)clist[row * MAXC];
                continue;
            }
            const float4* rp = (const float4*)(rptr + (size_t)row * DDIM) + lane * 4;
            float4 rv0 = rp[0], rv1 = rp[1], rv2 = rp[2], rv3 = rp[3];
            float rsqv = rsq_s[row];
            unsigned long long best = ~0ull;
            if (cnt <= MAXC) {
                for (int q = 0; q < cnt; ++q) {
                    int code = clist[row * MAXC + q];
                    float s = dot512(cbl + (size_t)code * DDIM, lane, rv0, rv1, rv2, rv3);
                    float d = (rsqv + csq_s[code]) - 2.0f * s;
                    unsigned long long key =
                        ((unsigned long long)__float_as_uint(d) << 32) | (unsigned)code;
                    if (key < best) best = key;
                }
            } else {
                // guaranteed-correct slow path: scan all codes exactly
                for (int code = 0; code < KCB; ++code) {
                    float s = dot512(cbl + (size_t)code * DDIM, lane, rv0, rv1, rv2, rv3);
                    float d = (rsqv + csq_s[code]) - 2.0f * s;
                    unsigned long long key =
                        ((unsigned long long)__float_as_uint(d) << 32) | (unsigned)code;
                    if (key < best) best = key;
                }
            }
            if (lane == 0) rowkey[row] = best;
        }
        __syncthreads();

        // ---- fused update, row-per-quad layout (no shuffles) ----
        if (l < LLEV - 1) {
            // v = r - e (exact fp32) -> g_res, bf16 A smem, R1-order rsq partials
            unsigned idx = (unsigned)(rowkey[urow] & 0xffffffffu);
            const float4* ep = (const float4*)(cbl + (size_t)idx * DDIM) + useg * 32;
            const float4* rp = (const float4*)(rptr + (size_t)urow * DDIM) + useg * 32;
            float4* gp = (float4*)(g_res + (size_t)(n0 + urow) * DDIM) + useg * 32;
            char* ap = smb + SM_A + urow * ASTR + useg * 256;
            float s = 0.f;
            #pragma unroll 8
            for (int m = 0; m < 32; ++m) {
                float4 e = ep[m];
                float4 v = rp[m];
                v.x -= e.x; v.y -= e.y; v.z -= e.z; v.w -= e.w;
                gp[m] = v;
                __nv_bfloat162 b0 = __floats2bfloat162_rn(v.x, v.y);
                __nv_bfloat162 b1 = __floats2bfloat162_rn(v.z, v.w);
                uint2 u;
                u.x = *(uint32_t*)&b0;
                u.y = *(uint32_t*)&b1;
                *(uint2*)(ap + m * 8) = u;
                s = fmaf(v.x, v.x, s); s = fmaf(v.y, v.y, s);
                s = fmaf(v.z, v.z, s); s = fmaf(v.w, v.w, s);
            }
            part[useg * ROWS + urow] = s;
            __syncthreads();
            if (t < ROWS)
                rsq_s[t] = ((part[t] + part[ROWS + t]) + part[2 * ROWS + t])
                           + part[3 * ROWS + t];
        } else {
            // last level: quant = inputs - residual_final, written once
            unsigned idx = (unsigned)(rowkey[urow] & 0xffffffffu);
            const float4* ep = (const float4*)(cbl + (size_t)idx * DDIM) + useg * 32;
            const float4* rp = (const float4*)(rptr + (size_t)urow * DDIM) + useg * 32;
            const float4* ip = (const float4*)(inp + (size_t)(n0 + urow) * DDIM) + useg * 32;
            float4* qp = (float4*)(outq + (size_t)(n0 + urow) * DDIM) + useg * 32;
            #pragma unroll 8
            for (int m = 0; m < 32; ++m) {
                float4 e = ep[m];
                float4 r = rp[m];
                r.x -= e.x; r.y -= e.y; r.z -= e.z; r.w -= e.w;
                float4 in = ip[m];
                float4 q;
                q.x = in.x - r.x; q.y = in.y - r.y;
                q.z = in.z - r.z; q.w = in.w - r.w;
                qp[m] = q;
            }
        }
        if (write_codes && t < ROWS) {
            unsigned idx = (unsigned)(rowkey[t] & 0xffffffffu);
            outc[(size_t)(n0 + t) * LLEV + l] = (float)idx;
        }
        __syncthreads();
    }
}

// ---------------------------------------------------------------------------
extern "C" void kernel_launch(void* const* d_in, const int* in_sizes, int n_in,
                              void* d_out, int out_size) {
    const float* inp = (const float*)d_in[0];
    const float* cb  = (const float*)d_in[1];
    if (n_in >= 2 && in_sizes[0] == LLEV * KCB * DDIM && in_sizes[1] == NROWS * DDIM) {
        const float* tmp = inp; inp = cb; cb = tmp;
    }
    float* outq = (float*)d_out;
    float* outc = nullptr;
    int write_codes = 0;
    long long quant_elems = (long long)NROWS * DDIM;
    if ((long long)out_size >= quant_elems + (long long)NROWS * LLEV) {
        write_codes = 1;
        outc = outq + quant_elems;
    }

    prep_kernel<<<(LLEV * KCB * 32 + 255) / 256, 256>>>(cb);

    cudaFuncSetAttribute(rq_kernel, cudaFuncAttributeMaxDynamicSharedMemorySize, SM_TOTAL);
    rq_kernel<<<NROWS / ROWS, TPB, SM_TOTAL>>>(inp, cb, outq, outc, write_codes);
}

// round 14
// speedup vs baseline: 1.3558x; 1.3558x over previous
#include <cuda_runtime.h>
#include <cuda_bf16.h>
#include <cstdint>

// Residual quantization, N=65536, D=512, K=1024, L=4.  (R12 + cnt==1 shortcut)
// Phase 1: bf16 mma.sync (m16n8k16), ldmatrix feed, per-cq distance-2 cp.async
//          pipeline (exact R6 schedule).
// Phase 2: margin-collect -> exact fp32 rescore; cnt==1 short-circuits (sole
//          within-margin candidate IS the argmin); overflow -> full exact scan.
// Update:  fused (R12 layout, coalesced): v = r - e (exact fp32) feeds g_res,
//          bf16 A-smem, and warp-reduced rsq partials. quant written once.

#define NROWS 65536
#define DDIM  512
#define KCB   1024
#define LLEV  4
#define ROWS  64
#define TPB   256
#define ASTR  1040        // A row stride bytes (1024 data + 16 pad, conflict-free)
#define MARGIN 0.02f
#define MAXC  16

#define SM_A      0        // 64*1040      = 66560
#define SM_B      66560    // 2*16384      -> 99328 (swizzled, no pad)
#define SM_CSQ    99328    // 4096         -> 103424
#define SM_RSQ    103424   // 256          -> 103680
#define SM_RUNMIN 103680   // 256          -> 103936
#define SM_CCNT   103936   // 256          -> 104192
#define SM_CLIST  104192   // 64*16*4=4096 -> 108288 (PART aliases first 1KB)
#define SM_ROWKEY 108288   // 512          -> 108800
#define SM_TOTAL  108800

__device__ float g_csq[LLEV * KCB];
__device__ float g_res[(size_t)NROWS * DDIM];
__device__ __align__(16) __nv_bfloat16 g_cb16[(size_t)LLEV * KCB * DDIM];

__device__ __forceinline__ uint32_t smem_u32(const void* p) {
    uint32_t a;
    asm("{ .reg .u64 t; cvta.to.shared.u64 t, %1; cvt.u32.u64 %0, t; }" : "=r"(a) : "l"(p));
    return a;
}
__device__ __forceinline__ void cpa16(uint32_t dst, const void* src) {
    asm volatile("cp.async.cg.shared.global [%0], [%1], 16;" :: "r"(dst), "l"(src));
}
__device__ __forceinline__ void cpa_commit() {
    asm volatile("cp.async.commit_group;" ::: "memory");
}
__device__ __forceinline__ void ldm_x4(uint32_t addr, uint32_t* r) {
    asm volatile("ldmatrix.sync.aligned.m8n8.x4.shared.b16 {%0,%1,%2,%3}, [%4];"
                 : "=r"(r[0]), "=r"(r[1]), "=r"(r[2]), "=r"(r[3]) : "r"(addr));
}

#define MMA16816(c, a0, a1, a2, a3, b0, b1)                                     \
    asm volatile(                                                               \
        "mma.sync.aligned.m16n8k16.row.col.f32.bf16.bf16.f32 "                  \
        "{%0,%1,%2,%3}, {%4,%5,%6,%7}, {%8,%9}, {%0,%1,%2,%3};"                 \
        : "+f"((c)[0]), "+f"((c)[1]), "+f"((c)[2]), "+f"((c)[3])                \
        : "r"(a0), "r"(a1), "r"(a2), "r"(a3), "r"(b0), "r"(b1))

__device__ __forceinline__ float dot512(const float* cbrow, int lane,
                                        float4 rv0, float4 rv1, float4 rv2, float4 rv3) {
    const float4* cp = (const float4*)cbrow + lane * 4;
    float4 c0 = cp[0], c1 = cp[1], c2 = cp[2], c3 = cp[3];
    float s = 0.f;
    s = fmaf(rv0.x, c0.x, s); s = fmaf(rv0.y, c0.y, s);
    s = fmaf(rv0.z, c0.z, s); s = fmaf(rv0.w, c0.w, s);
    s = fmaf(rv1.x, c1.x, s); s = fmaf(rv1.y, c1.y, s);
    s = fmaf(rv1.z, c1.z, s); s = fmaf(rv1.w, c1.w, s);
    s = fmaf(rv2.x, c2.x, s); s = fmaf(rv2.y, c2.y, s);
    s = fmaf(rv2.z, c2.z, s); s = fmaf(rv2.w, c2.w, s);
    s = fmaf(rv3.x, c3.x, s); s = fmaf(rv3.y, c3.y, s);
    s = fmaf(rv3.z, c3.z, s); s = fmaf(rv3.w, c3.w, s);
    #pragma unroll
    for (int o = 16; o; o >>= 1) s += __shfl_xor_sync(0xffffffffu, s, o);
    return s;
}

// ---------------------------------------------------------------------------
// prep: exact fp32 csq (R1 order) + bf16-rounded codebook copy
// ---------------------------------------------------------------------------
__global__ void prep_kernel(const float* __restrict__ cb) {
    int warp = (blockIdx.x * blockDim.x + threadIdx.x) >> 5;
    int lane = threadIdx.x & 31;
    if (warp >= LLEV * KCB) return;
    const float4* p = (const float4*)(cb + (size_t)warp * DDIM);
    __nv_bfloat162* o = (__nv_bfloat162*)(g_cb16 + (size_t)warp * DDIM);
    float s = 0.f;
    #pragma unroll
    for (int i = lane; i < DDIM / 4; i += 32) {
        float4 v = p[i];
        s = fmaf(v.x, v.x, s);
        s = fmaf(v.y, v.y, s);
        s = fmaf(v.z, v.z, s);
        s = fmaf(v.w, v.w, s);
        o[2 * i]     = __floats2bfloat162_rn(v.x, v.y);
        o[2 * i + 1] = __floats2bfloat162_rn(v.z, v.w);
    }
    #pragma unroll
    for (int q = 16; q; q >>= 1) s += __shfl_down_sync(0xffffffffu, s, q);
    if (lane == 0) g_csq[warp] = s;
}

// ---------------------------------------------------------------------------
// B tile fill: 256 codes x 32 d (64 bytes), XOR-swizzled 16B segments
// ---------------------------------------------------------------------------
__device__ __forceinline__ void bload(uint32_t sma, const __nv_bfloat16* cb16l,
                                      int buf, int cq, int dc, int t) {
    uint32_t dst0 = sma + SM_B + buf * 16384;
    const char* src0 = (const char*)cb16l + (size_t)cq * 256 * 1024 + dc * 64;
    #pragma unroll
    for (int i = 0; i < 4; ++i) {
        int e = t + i * TPB;            // 0..1023
        int code = e >> 2, seg = e & 3;
        uint32_t off = (uint32_t)(code * 64) + (uint32_t)((seg ^ ((code >> 1) & 3)) << 4);
        cpa16(dst0 + off, src0 + (size_t)code * 1024 + seg * 16);
    }
}

// ---------------------------------------------------------------------------
__global__ void __launch_bounds__(TPB, 2)
rq_kernel(const float* __restrict__ inp, const float* __restrict__ cb,
          float* __restrict__ outq, float* __restrict__ outc, int write_codes)
{
    extern __shared__ char smb[];
    float* csq_s = (float*)(smb + SM_CSQ);
    float* rsq_s = (float*)(smb + SM_RSQ);
    float* part  = (float*)(smb + SM_CLIST);   // aliased: dead before clist is used
    uint32_t* runmin = (uint32_t*)(smb + SM_RUNMIN);
    uint32_t* ccnt   = (uint32_t*)(smb + SM_CCNT);
    int* clist       = (int*)(smb + SM_CLIST);
    unsigned long long* rowkey = (unsigned long long*)(smb + SM_ROWKEY);

    const int t = threadIdx.x, lane = t & 31, wid = t >> 5;
    const int gid = lane >> 2, tig = lane & 3;
    const int wrow = wid & 1, wcol = wid >> 1;
    const int n0 = blockIdx.x * ROWS;
    const uint32_t sma = smem_u32(smb);
    const int l16 = lane & 15, lhi4 = lane >> 4;

    for (int l = 0; l < LLEV; ++l) {
        const float* rptr = (l ? g_res : inp) + (size_t)n0 * DDIM;
        const float* cbl = cb + (size_t)l * KCB * DDIM;
        const __nv_bfloat16* cb16l = g_cb16 + (size_t)l * KCB * DDIM;

        for (int i = t; i < KCB; i += TPB) csq_s[i] = g_csq[l * KCB + i];
        if (t < ROWS) { runmin[t] = 0x7f800000u; ccnt[t] = 0u; }

        if (l == 0) {
            // level 0 only: convert input -> bf16 A smem; exact rsq partials
            int row = t >> 2, seg = t & 3;
            const float4* rp = (const float4*)(rptr + (size_t)row * DDIM + seg * 128);
            char* ap = smb + SM_A + row * ASTR + seg * 256;
            float s = 0.f;
            #pragma unroll
            for (int m = 0; m < 16; ++m) {
                float4 v0 = rp[2 * m], v1 = rp[2 * m + 1];
                s = fmaf(v0.x, v0.x, s); s = fmaf(v0.y, v0.y, s);
                s = fmaf(v0.z, v0.z, s); s = fmaf(v0.w, v0.w, s);
                s = fmaf(v1.x, v1.x, s); s = fmaf(v1.y, v1.y, s);
                s = fmaf(v1.z, v1.z, s); s = fmaf(v1.w, v1.w, s);
                __nv_bfloat162 b0 = __floats2bfloat162_rn(v0.x, v0.y);
                __nv_bfloat162 b1 = __floats2bfloat162_rn(v0.z, v0.w);
                __nv_bfloat162 b2 = __floats2bfloat162_rn(v1.x, v1.y);
                __nv_bfloat162 b3 = __floats2bfloat162_rn(v1.z, v1.w);
                uint4 u;
                u.x = *(uint32_t*)&b0; u.y = *(uint32_t*)&b1;
                u.z = *(uint32_t*)&b2; u.w = *(uint32_t*)&b3;
                *(uint4*)(ap + m * 16) = u;
            }
            part[seg * ROWS + row] = s;
            __syncthreads();
            if (t < ROWS)
                rsq_s[t] = ((part[t] + part[ROWS + t]) + part[2 * ROWS + t])
                           + part[3 * ROWS + t];
        }
        // (l>0: A smem + rsq_s were produced by the previous level's update)
        __syncthreads();

        // ---- phase 1: approximate GEMM (exact R6 schedule) + margin collection ----
        for (int cq = 0; cq < 4; ++cq) {
            float acc[2][8][4];
            #pragma unroll
            for (int i = 0; i < 2; ++i)
                #pragma unroll
                for (int j = 0; j < 8; ++j)
                    #pragma unroll
                    for (int k = 0; k < 4; ++k) acc[i][j][k] = 0.f;

            bload(sma, cb16l, 0, cq, 0, t); cpa_commit();
            bload(sma, cb16l, 1, cq, 1, t); cpa_commit();

            const uint32_t aaddr0 = sma + SM_A + (wrow * 32 + l16) * ASTR + (lhi4 << 4);
            for (int dc = 0; dc < 16; ++dc) {
                asm volatile("cp.async.wait_group 1;" ::: "memory");
                __syncthreads();
                const uint32_t bbase = sma + SM_B + (dc & 1) * 16384;
                #pragma unroll
                for (int ks = 0; ks < 2; ++ks) {
                    uint32_t a0[4], a1[4];
                    ldm_x4(aaddr0 + dc * 64 + ks * 32, a0);
                    ldm_x4(aaddr0 + 16 * ASTR + dc * 64 + ks * 32, a1);
                    const int bseg = ks * 2 + lhi4;
                    #pragma unroll
                    for (int j2 = 0; j2 < 4; ++j2) {
                        int brow = wcol * 64 + j2 * 16 + l16;
                        uint32_t baddr = bbase + brow * 64
                                         + ((bseg ^ ((brow >> 1) & 3)) << 4);
                        uint32_t b[4];
                        ldm_x4(baddr, b);
                        MMA16816(acc[0][2 * j2],     a0[0], a0[1], a0[2], a0[3], b[0], b[2]);
                        MMA16816(acc[0][2 * j2 + 1], a0[0], a0[1], a0[2], a0[3], b[1], b[3]);
                        MMA16816(acc[1][2 * j2],     a1[0], a1[1], a1[2], a1[3], b[0], b[2]);
                        MMA16816(acc[1][2 * j2 + 1], a1[0], a1[1], a1[2], a1[3], b[1], b[3]);
                    }
                }
                __syncthreads();
                if (dc + 2 < 16) bload(sma, cb16l, dc & 1, cq, dc + 2, t);
                cpa_commit();
            }

            // scores in place of acc; update running row minima
            const int cqbase = cq * 256;
            float rsqv[2][2], smin[2][2];
            #pragma unroll
            for (int i = 0; i < 2; ++i)
                #pragma unroll
                for (int h = 0; h < 2; ++h) {
                    rsqv[i][h] = rsq_s[wrow * 32 + i * 16 + gid + h * 8];
                    smin[i][h] = __int_as_float(0x7f800000);
                }
            #pragma unroll
            for (int i = 0; i < 2; ++i)
                #pragma unroll
                for (int j = 0; j < 8; ++j) {
                    int code0 = cqbase + wcol * 64 + j * 8 + tig * 2;
                    float cq0 = csq_s[code0], cq1 = csq_s[code0 + 1];
                    float s0 = (rsqv[i][0] + cq0) - 2.0f * acc[i][j][0];
                    float s1 = (rsqv[i][0] + cq1) - 2.0f * acc[i][j][1];
                    float s2 = (rsqv[i][1] + cq0) - 2.0f * acc[i][j][2];
                    float s3 = (rsqv[i][1] + cq1) - 2.0f * acc[i][j][3];
                    acc[i][j][0] = s0; acc[i][j][1] = s1;
                    acc[i][j][2] = s2; acc[i][j][3] = s3;
                    smin[i][0] = fminf(smin[i][0], fminf(s0, s1));
                    smin[i][1] = fminf(smin[i][1], fminf(s2, s3));
                }
            #pragma unroll
            for (int i = 0; i < 2; ++i)
                #pragma unroll
                for (int h = 0; h < 2; ++h)
                    atomicMin(&runmin[wrow * 32 + i * 16 + gid + h * 8],
                              __float_as_uint(smin[i][h]));
            __syncthreads();
            // collect candidates within margin of running min
            #pragma unroll
            for (int i = 0; i < 2; ++i) {
                float thr0 = __uint_as_float(runmin[wrow * 32 + i * 16 + gid]) + MARGIN;
                float thr1 = __uint_as_float(runmin[wrow * 32 + i * 16 + gid + 8]) + MARGIN;
                int row0 = wrow * 32 + i * 16 + gid, row1 = row0 + 8;
                #pragma unroll
                for (int j = 0; j < 8; ++j) {
                    int code0 = cqbase + wcol * 64 + j * 8 + tig * 2;
                    if (acc[i][j][0] < thr0) {
                        uint32_t sl = atomicAdd(&ccnt[row0], 1u);
                        if (sl < MAXC) clist[row0 * MAXC + sl] = code0;
                    }
                    if (acc[i][j][1] < thr0) {
                        uint32_t sl = atomicAdd(&ccnt[row0], 1u);
                        if (sl < MAXC) clist[row0 * MAXC + sl] = code0 + 1;
                    }
                    if (acc[i][j][2] < thr1) {
                        uint32_t sl = atomicAdd(&ccnt[row1], 1u);
                        if (sl < MAXC) clist[row1 * MAXC + sl] = code0;
                    }
                    if (acc[i][j][3] < thr1) {
                        uint32_t sl = atomicAdd(&ccnt[row1], 1u);
                        if (sl < MAXC) clist[row1 * MAXC + sl] = code0 + 1;
                    }
                }
            }
            __syncthreads();
        }

        // ---- phase 2: cnt==1 shortcut; else exact rescore / full scan ----
        for (int r8 = 0; r8 < 8; ++r8) {
            int row = wid * 8 + r8;
            int cnt = (int)ccnt[row];
            if (cnt == 1) {
                // sole within-margin candidate IS the argmin (min always collected)
                if (lane == 0)
                    rowkey[row] = (unsigned long long)(unsigned)clist[row * MAXC];
                continue;
            }
            const float4* rp = (const float4*)(rptr + (size_t)row * DDIM) + lane * 4;
            float4 rv0 = rp[0], rv1 = rp[1], rv2 = rp[2], rv3 = rp[3];
            float rsqv = rsq_s[row];
            unsigned long long best = ~0ull;
            if (cnt <= MAXC) {
                for (int q = 0; q < cnt; ++q) {
                    int code = clist[row * MAXC + q];
                    float s = dot512(cbl + (size_t)code * DDIM, lane, rv0, rv1, rv2, rv3);
                    float d = (rsqv + csq_s[code]) - 2.0f * s;
                    unsigned long long key =
                        ((unsigned long long)__float_as_uint(d) << 32) | (unsigned)code;
                    if (key < best) best = key;
                }
            } else {
                // guaranteed-correct slow path: scan all codes exactly
                for (int code = 0; code < KCB; ++code) {
                    float s = dot512(cbl + (size_t)code * DDIM, lane, rv0, rv1, rv2, rv3);
                    float d = (rsqv + csq_s[code]) - 2.0f * s;
                    unsigned long long key =
                        ((unsigned long long)__float_as_uint(d) << 32) | (unsigned)code;
                    if (key < best) best = key;
                }
            }
            if (lane == 0) rowkey[row] = best;
        }
        __syncthreads();

        // ---- fused update (R12 layout: coalesced, shuffle rsq reduce) ----
        if (l < LLEV - 1) {
            // v = r - e (exact fp32) -> g_res, bf16 A smem, rsq partials
            #pragma unroll 4
            for (int k = 0; k < 32; ++k) {
                int i = t + k * TPB;
                int row = i >> 7, dq = i & 127;
                unsigned idx = (unsigned)(rowkey[row] & 0xffffffffu);
                float4 e = ((const float4*)(cbl + (size_t)idx * DDIM))[dq];
                float4 v = ((const float4*)(rptr + (size_t)row * DDIM))[dq];
                v.x -= e.x; v.y -= e.y; v.z -= e.z; v.w -= e.w;
                ((float4*)(g_res + (size_t)(n0 + row) * DDIM))[dq] = v;
                __nv_bfloat162 b0 = __floats2bfloat162_rn(v.x, v.y);
                __nv_bfloat162 b1 = __floats2bfloat162_rn(v.z, v.w);
                uint2 u;
                u.x = *(uint32_t*)&b0;
                u.y = *(uint32_t*)&b1;
                *(uint2*)(smb + SM_A + row * ASTR + dq * 8) = u;
                float s = fmaf(v.x, v.x, fmaf(v.y, v.y, fmaf(v.z, v.z, v.w * v.w)));
                #pragma unroll
                for (int o = 16; o; o >>= 1) s += __shfl_xor_sync(0xffffffffu, s, o);
                if (lane == 0) part[(wid & 3) * ROWS + row] = s;  // unique slot
            }
            __syncthreads();
            if (t < ROWS)
                rsq_s[t] = ((part[t] + part[ROWS + t]) + part[2 * ROWS + t])
                           + part[3 * ROWS + t];
        } else {
            // last level: quant = inputs - residual_final, written once
            const float* inb = inp + (size_t)n0 * DDIM;
            #pragma unroll 4
            for (int k = 0; k < 32; ++k) {
                int i = t + k * TPB;
                int row = i >> 7, dq = i & 127;
                unsigned idx = (unsigned)(rowkey[row] & 0xffffffffu);
                float4 e = ((const float4*)(cbl + (size_t)idx * DDIM))[dq];
                float4 r = ((const float4*)(rptr + (size_t)row * DDIM))[dq];
                r.x -= e.x; r.y -= e.y; r.z -= e.z; r.w -= e.w;
                float4 in = ((const float4*)(inb + (size_t)row * DDIM))[dq];
                float4 q;
                q.x = in.x - r.x; q.y = in.y - r.y;
                q.z = in.z - r.z; q.w = in.w - r.w;
                ((float4*)(outq + (size_t)(n0 + row) * DDIM))[dq] = q;
            }
        }
        if (write_codes && t < ROWS) {
            unsigned idx = (unsigned)(rowkey[t] & 0xffffffffu);
            outc[(size_t)(n0 + t) * LLEV + l] = (float)idx;
        }
        __syncthreads();
    }
}

// ---------------------------------------------------------------------------
extern "C" void kernel_launch(void* const* d_in, const int* in_sizes, int n_in,
                              void* d_out, int out_size) {
    const float* inp = (const float*)d_in[0];
    const float* cb  = (const float*)d_in[1];
    if (n_in >= 2 && in_sizes[0] == LLEV * KCB * DDIM && in_sizes[1] == NROWS * DDIM) {
        const float* tmp = inp; inp = cb; cb = tmp;
    }
    float* outq = (float*)d_out;
    float* outc = nullptr;
    int write_codes = 0;
    long long quant_elems = (long long)NROWS * DDIM;
    if ((long long)out_size >= quant_elems + (long long)NROWS * LLEV) {
        write_codes = 1;
        outc = outq + quant_elems;
    }

    prep_kernel<<<(LLEV * KCB * 32 + 255) / 256, 256>>>(cb);

    cudaFuncSetAttribute(rq_kernel, cudaFuncAttributeMaxDynamicSharedMemorySize, SM_TOTAL);
    rq_kernel<<<NROWS / ROWS, TPB, SM_TOTAL>>>(inp, cb, outq, outc, write_codes);
}

// round 15
// speedup vs baseline: 1.3665x; 1.0079x over previous
#include <cuda_runtime.h>
#include <cuda_bf16.h>
#include <cstdint>

// Residual quantization, N=65536, D=512, K=1024, L=4.
// (R14 + single change: trailing per-cq collect barrier removed)
// Phase 1: bf16 mma.sync (m16n8k16), ldmatrix feed, per-cq distance-2 cp.async
//          pipeline (exact R6 schedule).
// Phase 2: margin-collect -> exact fp32 rescore; cnt==1 short-circuits (sole
//          within-margin candidate IS the argmin); overflow -> full exact scan.
// Update:  fused (coalesced): v = r - e (exact fp32) feeds g_res, bf16 A-smem,
//          and warp-reduced rsq partials. quant written once at the last level.

#define NROWS 65536
#define DDIM  512
#define KCB   1024
#define LLEV  4
#define ROWS  64
#define TPB   256
#define ASTR  1040        // A row stride bytes (1024 data + 16 pad, conflict-free)
#define MARGIN 0.02f
#define MAXC  16

#define SM_A      0        // 64*1040      = 66560
#define SM_B      66560    // 2*16384      -> 99328 (swizzled, no pad)
#define SM_CSQ    99328    // 4096         -> 103424
#define SM_RSQ    103424   // 256          -> 103680
#define SM_RUNMIN 103680   // 256          -> 103936
#define SM_CCNT   103936   // 256          -> 104192
#define SM_CLIST  104192   // 64*16*4=4096 -> 108288 (PART aliases first 1KB)
#define SM_ROWKEY 108288   // 512          -> 108800
#define SM_TOTAL  108800

__device__ float g_csq[LLEV * KCB];
__device__ float g_res[(size_t)NROWS * DDIM];
__device__ __align__(16) __nv_bfloat16 g_cb16[(size_t)LLEV * KCB * DDIM];

__device__ __forceinline__ uint32_t smem_u32(const void* p) {
    uint32_t a;
    asm("{ .reg .u64 t; cvta.to.shared.u64 t, %1; cvt.u32.u64 %0, t; }" : "=r"(a) : "l"(p));
    return a;
}
__device__ __forceinline__ void cpa16(uint32_t dst, const void* src) {
    asm volatile("cp.async.cg.shared.global [%0], [%1], 16;" :: "r"(dst), "l"(src));
}
__device__ __forceinline__ void cpa_commit() {
    asm volatile("cp.async.commit_group;" ::: "memory");
}
__device__ __forceinline__ void ldm_x4(uint32_t addr, uint32_t* r) {
    asm volatile("ldmatrix.sync.aligned.m8n8.x4.shared.b16 {%0,%1,%2,%3}, [%4];"
                 : "=r"(r[0]), "=r"(r[1]), "=r"(r[2]), "=r"(r[3]) : "r"(addr));
}

#define MMA16816(c, a0, a1, a2, a3, b0, b1)                                     \
    asm volatile(                                                               \
        "mma.sync.aligned.m16n8k16.row.col.f32.bf16.bf16.f32 "                  \
        "{%0,%1,%2,%3}, {%4,%5,%6,%7}, {%8,%9}, {%0,%1,%2,%3};"                 \
        : "+f"((c)[0]), "+f"((c)[1]), "+f"((c)[2]), "+f"((c)[3])                \
        : "r"(a0), "r"(a1), "r"(a2), "r"(a3), "r"(b0), "r"(b1))

__device__ __forceinline__ float dot512(const float* cbrow, int lane,
                                        float4 rv0, float4 rv1, float4 rv2, float4 rv3) {
    const float4* cp = (const float4*)cbrow + lane * 4;
    float4 c0 = cp[0], c1 = cp[1], c2 = cp[2], c3 = cp[3];
    float s = 0.f;
    s = fmaf(rv0.x, c0.x, s); s = fmaf(rv0.y, c0.y, s);
    s = fmaf(rv0.z, c0.z, s); s = fmaf(rv0.w, c0.w, s);
    s = fmaf(rv1.x, c1.x, s); s = fmaf(rv1.y, c1.y, s);
    s = fmaf(rv1.z, c1.z, s); s = fmaf(rv1.w, c1.w, s);
    s = fmaf(rv2.x, c2.x, s); s = fmaf(rv2.y, c2.y, s);
    s = fmaf(rv2.z, c2.z, s); s = fmaf(rv2.w, c2.w, s);
    s = fmaf(rv3.x, c3.x, s); s = fmaf(rv3.y, c3.y, s);
    s = fmaf(rv3.z, c3.z, s); s = fmaf(rv3.w, c3.w, s);
    #pragma unroll
    for (int o = 16; o; o >>= 1) s += __shfl_xor_sync(0xffffffffu, s, o);
    return s;
}

// ---------------------------------------------------------------------------
// prep: exact fp32 csq (R1 order) + bf16-rounded codebook copy
// ---------------------------------------------------------------------------
__global__ void prep_kernel(const float* __restrict__ cb) {
    int warp = (blockIdx.x * blockDim.x + threadIdx.x) >> 5;
    int lane = threadIdx.x & 31;
    if (warp >= LLEV * KCB) return;
    const float4* p = (const float4*)(cb + (size_t)warp * DDIM);
    __nv_bfloat162* o = (__nv_bfloat162*)(g_cb16 + (size_t)warp * DDIM);
    float s = 0.f;
    #pragma unroll
    for (int i = lane; i < DDIM / 4; i += 32) {
        float4 v = p[i];
        s = fmaf(v.x, v.x, s);
        s = fmaf(v.y, v.y, s);
        s = fmaf(v.z, v.z, s);
        s = fmaf(v.w, v.w, s);
        o[2 * i]     = __floats2bfloat162_rn(v.x, v.y);
        o[2 * i + 1] = __floats2bfloat162_rn(v.z, v.w);
    }
    #pragma unroll
    for (int q = 16; q; q >>= 1) s += __shfl_down_sync(0xffffffffu, s, q);
    if (lane == 0) g_csq[warp] = s;
}

// ---------------------------------------------------------------------------
// B tile fill: 256 codes x 32 d (64 bytes), XOR-swizzled 16B segments
// ---------------------------------------------------------------------------
__device__ __forceinline__ void bload(uint32_t sma, const __nv_bfloat16* cb16l,
                                      int buf, int cq, int dc, int t) {
    uint32_t dst0 = sma + SM_B + buf * 16384;
    const char* src0 = (const char*)cb16l + (size_t)cq * 256 * 1024 + dc * 64;
    #pragma unroll
    for (int i = 0; i < 4; ++i) {
        int e = t + i * TPB;            // 0..1023
        int code = e >> 2, seg = e & 3;
        uint32_t off = (uint32_t)(code * 64) + (uint32_t)((seg ^ ((code >> 1) & 3)) << 4);
        cpa16(dst0 + off, src0 + (size_t)code * 1024 + seg * 16);
    }
}

// ---------------------------------------------------------------------------
__global__ void __launch_bounds__(TPB, 2)
rq_kernel(const float* __restrict__ inp, const float* __restrict__ cb,
          float* __restrict__ outq, float* __restrict__ outc, int write_codes)
{
    extern __shared__ char smb[];
    float* csq_s = (float*)(smb + SM_CSQ);
    float* rsq_s = (float*)(smb + SM_RSQ);
    float* part  = (float*)(smb + SM_CLIST);   // aliased: dead before clist is used
    uint32_t* runmin = (uint32_t*)(smb + SM_RUNMIN);
    uint32_t* ccnt   = (uint32_t*)(smb + SM_CCNT);
    int* clist       = (int*)(smb + SM_CLIST);
    unsigned long long* rowkey = (unsigned long long*)(smb + SM_ROWKEY);

    const int t = threadIdx.x, lane = t & 31, wid = t >> 5;
    const int gid = lane >> 2, tig = lane & 3;
    const int wrow = wid & 1, wcol = wid >> 1;
    const int n0 = blockIdx.x * ROWS;
    const uint32_t sma = smem_u32(smb);
    const int l16 = lane & 15, lhi4 = lane >> 4;

    for (int l = 0; l < LLEV; ++l) {
        const float* rptr = (l ? g_res : inp) + (size_t)n0 * DDIM;
        const float* cbl = cb + (size_t)l * KCB * DDIM;
        const __nv_bfloat16* cb16l = g_cb16 + (size_t)l * KCB * DDIM;

        for (int i = t; i < KCB; i += TPB) csq_s[i] = g_csq[l * KCB + i];
        if (t < ROWS) { runmin[t] = 0x7f800000u; ccnt[t] = 0u; }

        if (l == 0) {
            // level 0 only: convert input -> bf16 A smem; exact rsq partials
            int row = t >> 2, seg = t & 3;
            const float4* rp = (const float4*)(rptr + (size_t)row * DDIM + seg * 128);
            char* ap = smb + SM_A + row * ASTR + seg * 256;
            float s = 0.f;
            #pragma unroll
            for (int m = 0; m < 16; ++m) {
                float4 v0 = rp[2 * m], v1 = rp[2 * m + 1];
                s = fmaf(v0.x, v0.x, s); s = fmaf(v0.y, v0.y, s);
                s = fmaf(v0.z, v0.z, s); s = fmaf(v0.w, v0.w, s);
                s = fmaf(v1.x, v1.x, s); s = fmaf(v1.y, v1.y, s);
                s = fmaf(v1.z, v1.z, s); s = fmaf(v1.w, v1.w, s);
                __nv_bfloat162 b0 = __floats2bfloat162_rn(v0.x, v0.y);
                __nv_bfloat162 b1 = __floats2bfloat162_rn(v0.z, v0.w);
                __nv_bfloat162 b2 = __floats2bfloat162_rn(v1.x, v1.y);
                __nv_bfloat162 b3 = __floats2bfloat162_rn(v1.z, v1.w);
                uint4 u;
                u.x = *(uint32_t*)&b0; u.y = *(uint32_t*)&b1;
                u.z = *(uint32_t*)&b2; u.w = *(uint32_t*)&b3;
                *(uint4*)(ap + m * 16) = u;
            }
            part[seg * ROWS + row] = s;
            __syncthreads();
            if (t < ROWS)
                rsq_s[t] = ((part[t] + part[ROWS + t]) + part[2 * ROWS + t])
                           + part[3 * ROWS + t];
        }
        // (l>0: A smem + rsq_s were produced by the previous level's update)
        __syncthreads();

        // ---- phase 1: approximate GEMM (exact R6 schedule) + margin collection ----
        for (int cq = 0; cq < 4; ++cq) {
            float acc[2][8][4];
            #pragma unroll
            for (int i = 0; i < 2; ++i)
                #pragma unroll
                for (int j = 0; j < 8; ++j)
                    #pragma unroll
                    for (int k = 0; k < 4; ++k) acc[i][j][k] = 0.f;

            bload(sma, cb16l, 0, cq, 0, t); cpa_commit();
            bload(sma, cb16l, 1, cq, 1, t); cpa_commit();

            const uint32_t aaddr0 = sma + SM_A + (wrow * 32 + l16) * ASTR + (lhi4 << 4);
            for (int dc = 0; dc < 16; ++dc) {
                asm volatile("cp.async.wait_group 1;" ::: "memory");
                __syncthreads();
                const uint32_t bbase = sma + SM_B + (dc & 1) * 16384;
                #pragma unroll
                for (int ks = 0; ks < 2; ++ks) {
                    uint32_t a0[4], a1[4];
                    ldm_x4(aaddr0 + dc * 64 + ks * 32, a0);
                    ldm_x4(aaddr0 + 16 * ASTR + dc * 64 + ks * 32, a1);
                    const int bseg = ks * 2 + lhi4;
                    #pragma unroll
                    for (int j2 = 0; j2 < 4; ++j2) {
                        int brow = wcol * 64 + j2 * 16 + l16;
                        uint32_t baddr = bbase + brow * 64
                                         + ((bseg ^ ((brow >> 1) & 3)) << 4);
                        uint32_t b[4];
                        ldm_x4(baddr, b);
                        MMA16816(acc[0][2 * j2],     a0[0], a0[1], a0[2], a0[3], b[0], b[2]);
                        MMA16816(acc[0][2 * j2 + 1], a0[0], a0[1], a0[2], a0[3], b[1], b[3]);
                        MMA16816(acc[1][2 * j2],     a1[0], a1[1], a1[2], a1[3], b[0], b[2]);
                        MMA16816(acc[1][2 * j2 + 1], a1[0], a1[1], a1[2], a1[3], b[1], b[3]);
                    }
                }
                __syncthreads();
                if (dc + 2 < 16) bload(sma, cb16l, dc & 1, cq, dc + 2, t);
                cpa_commit();
            }

            // scores in place of acc; update running row minima
            const int cqbase = cq * 256;
            float rsqv[2][2], smin[2][2];
            #pragma unroll
            for (int i = 0; i < 2; ++i)
                #pragma unroll
                for (int h = 0; h < 2; ++h) {
                    rsqv[i][h] = rsq_s[wrow * 32 + i * 16 + gid + h * 8];
                    smin[i][h] = __int_as_float(0x7f800000);
                }
            #pragma unroll
            for (int i = 0; i < 2; ++i)
                #pragma unroll
                for (int j = 0; j < 8; ++j) {
                    int code0 = cqbase + wcol * 64 + j * 8 + tig * 2;
                    float cq0 = csq_s[code0], cq1 = csq_s[code0 + 1];
                    float s0 = (rsqv[i][0] + cq0) - 2.0f * acc[i][j][0];
                    float s1 = (rsqv[i][0] + cq1) - 2.0f * acc[i][j][1];
                    float s2 = (rsqv[i][1] + cq0) - 2.0f * acc[i][j][2];
                    float s3 = (rsqv[i][1] + cq1) - 2.0f * acc[i][j][3];
                    acc[i][j][0] = s0; acc[i][j][1] = s1;
                    acc[i][j][2] = s2; acc[i][j][3] = s3;
                    smin[i][0] = fminf(smin[i][0], fminf(s0, s1));
                    smin[i][1] = fminf(smin[i][1], fminf(s2, s3));
                }
            #pragma unroll
            for (int i = 0; i < 2; ++i)
                #pragma unroll
                for (int h = 0; h < 2; ++h)
                    atomicMin(&runmin[wrow * 32 + i * 16 + gid + h * 8],
                              __float_as_uint(smin[i][h]));
            __syncthreads();   // collect must see block-wide running min
            // collect candidates within margin of running min
            #pragma unroll
            for (int i = 0; i < 2; ++i) {
                float thr0 = __uint_as_float(runmin[wrow * 32 + i * 16 + gid]) + MARGIN;
                float thr1 = __uint_as_float(runmin[wrow * 32 + i * 16 + gid + 8]) + MARGIN;
                int row0 = wrow * 32 + i * 16 + gid, row1 = row0 + 8;
                #pragma unroll
                for (int j = 0; j < 8; ++j) {
                    int code0 = cqbase + wcol * 64 + j * 8 + tig * 2;
                    if (acc[i][j][0] < thr0) {
                        uint32_t sl = atomicAdd(&ccnt[row0], 1u);
                        if (sl < MAXC) clist[row0 * MAXC + sl] = code0;
                    }
                    if (acc[i][j][1] < thr0) {
                        uint32_t sl = atomicAdd(&ccnt[row0], 1u);
                        if (sl < MAXC) clist[row0 * MAXC + sl] = code0 + 1;
                    }
                    if (acc[i][j][2] < thr1) {
                        uint32_t sl = atomicAdd(&ccnt[row1], 1u);
                        if (sl < MAXC) clist[row1 * MAXC + sl] = code0;
                    }
                    if (acc[i][j][3] < thr1) {
                        uint32_t sl = atomicAdd(&ccnt[row1], 1u);
                        if (sl < MAXC) clist[row1 * MAXC + sl] = code0 + 1;
                    }
                }
            }
            // trailing barrier removed: nothing reads ccnt/clist until phase 2,
            // which is preceded by its own __syncthreads; runmin is monotonic
            // (atomicMin) so next cq's collect threshold is still conservative.
        }
        __syncthreads();   // clist/ccnt visible to phase 2

        // ---- phase 2: cnt==1 shortcut; else exact rescore / full scan ----
        for (int r8 = 0; r8 < 8; ++r8) {
            int row = wid * 8 + r8;
            int cnt = (int)ccnt[row];
            if (cnt == 1) {
                // sole within-margin candidate IS the argmin (min always collected)
                if (lane == 0)
                    rowkey[row] = (unsigned long long)(unsigned)clist[row * MAXC];
                continue;
            }
            const float4* rp = (const float4*)(rptr + (size_t)row * DDIM) + lane * 4;
            float4 rv0 = rp[0], rv1 = rp[1], rv2 = rp[2], rv3 = rp[3];
            float rsqv = rsq_s[row];
            unsigned long long best = ~0ull;
            if (cnt <= MAXC) {
                for (int q = 0; q < cnt; ++q) {
                    int code = clist[row * MAXC + q];
                    float s = dot512(cbl + (size_t)code * DDIM, lane, rv0, rv1, rv2, rv3);
                    float d = (rsqv + csq_s[code]) - 2.0f * s;
                    unsigned long long key =
                        ((unsigned long long)__float_as_uint(d) << 32) | (unsigned)code;
                    if (key < best) best = key;
                }
            } else {
                // guaranteed-correct slow path: scan all codes exactly
                for (int code = 0; code < KCB; ++code) {
                    float s = dot512(cbl + (size_t)code * DDIM, lane, rv0, rv1, rv2, rv3);
                    float d = (rsqv + csq_s[code]) - 2.0f * s;
                    unsigned long long key =
                        ((unsigned long long)__float_as_uint(d) << 32) | (unsigned)code;
                    if (key < best) best = key;
                }
            }
            if (lane == 0) rowkey[row] = best;
        }
        __syncthreads();

        // ---- fused update (coalesced layout, shuffle rsq reduce) ----
        if (l < LLEV - 1) {
            // v = r - e (exact fp32) -> g_res, bf16 A smem, rsq partials
            #pragma unroll 4
            for (int k = 0; k < 32; ++k) {
                int i = t + k * TPB;
                int row = i >> 7, dq = i & 127;
                unsigned idx = (unsigned)(rowkey[row] & 0xffffffffu);
                float4 e = ((const float4*)(cbl + (size_t)idx * DDIM))[dq];
                float4 v = ((const float4*)(rptr + (size_t)row * DDIM))[dq];
                v.x -= e.x; v.y -= e.y; v.z -= e.z; v.w -= e.w;
                ((float4*)(g_res + (size_t)(n0 + row) * DDIM))[dq] = v;
                __nv_bfloat162 b0 = __floats2bfloat162_rn(v.x, v.y);
                __nv_bfloat162 b1 = __floats2bfloat162_rn(v.z, v.w);
                uint2 u;
                u.x = *(uint32_t*)&b0;
                u.y = *(uint32_t*)&b1;
                *(uint2*)(smb + SM_A + row * ASTR + dq * 8) = u;
                float s = fmaf(v.x, v.x, fmaf(v.y, v.y, fmaf(v.z, v.z, v.w * v.w)));
                #pragma unroll
                for (int o = 16; o; o >>= 1) s += __shfl_xor_sync(0xffffffffu, s, o);
                if (lane == 0) part[(wid & 3) * ROWS + row] = s;  // unique slot
            }
            __syncthreads();
            if (t < ROWS)
                rsq_s[t] = ((part[t] + part[ROWS + t]) + part[2 * ROWS + t])
                           + part[3 * ROWS + t];
        } else {
            // last level: quant = inputs - residual_final, written once
            const float* inb = inp + (size_t)n0 * DDIM;
            #pragma unroll 4
            for (int k = 0; k < 32; ++k) {
                int i = t + k * TPB;
                int row = i >> 7, dq = i & 127;
                unsigned idx = (unsigned)(rowkey[row] & 0xffffffffu);
                float4 e = ((const float4*)(cbl + (size_t)idx * DDIM))[dq];
                float4 r = ((const float4*)(rptr + (size_t)row * DDIM))[dq];
                r.x -= e.x; r.y -= e.y; r.z -= e.z; r.w -= e.w;
                float4 in = ((const float4*)(inb + (size_t)row * DDIM))[dq];
                float4 q;
                q.x = in.x - r.x; q.y = in.y - r.y;
                q.z = in.z - r.z; q.w = in.w - r.w;
                ((float4*)(outq + (size_t)(n0 + row) * DDIM))[dq] = q;
            }
        }
        if (write_codes && t < ROWS) {
            unsigned idx = (unsigned)(rowkey[t] & 0xffffffffu);
            outc[(size_t)(n0 + t) * LLEV + l] = (float)idx;
        }
        __syncthreads();
    }
}

// ---------------------------------------------------------------------------
extern "C" void kernel_launch(void* const* d_in, const int* in_sizes, int n_in,
                              void* d_out, int out_size) {
    const float* inp = (const float*)d_in[0];
    const float* cb  = (const float*)d_in[1];
    if (n_in >= 2 && in_sizes[0] == LLEV * KCB * DDIM && in_sizes[1] == NROWS * DDIM) {
        const float* tmp = inp; inp = cb; cb = tmp;
    }
    float* outq = (float*)d_out;
    float* outc = nullptr;
    int write_codes = 0;
    long long quant_elems = (long long)NROWS * DDIM;
    if ((long long)out_size >= quant_elems + (long long)NROWS * LLEV) {
        write_codes = 1;
        outc = outq + quant_elems;
    }

    prep_kernel<<<(LLEV * KCB * 32 + 255) / 256, 256>>>(cb);

    cudaFuncSetAttribute(rq_kernel, cudaFuncAttributeMaxDynamicSharedMemorySize, SM_TOTAL);
    rq_kernel<<<NROWS / ROWS, TPB, SM_TOTAL>>>(inp, cb, outq, outc, write_codes);
}

// round 16
// speedup vs baseline: 1.4330x; 1.0487x over previous
#include <cuda_runtime.h>
#include <cuda_bf16.h>
#include <cstdint>

// Residual quantization, N=65536, D=512, K=1024, L=4.
// (R15 + single change: update loop restructured warp-per-row, shuffle-lean)
// Phase 1: bf16 mma.sync (m16n8k16), ldmatrix feed, per-cq distance-2 cp.async
//          pipeline (exact R6 schedule).
// Phase 2: margin-collect -> exact fp32 rescore; cnt==1 short-circuits (sole
//          within-margin candidate IS the argmin); overflow -> full exact scan.
// Update:  fused, warp-per-row coalesced: v = r - e (exact fp32) feeds g_res,
//          bf16 A-smem; one warp-reduce per row writes rsq_s directly.
//          quant written once at the last level.

#define NROWS 65536
#define DDIM  512
#define KCB   1024
#define LLEV  4
#define ROWS  64
#define TPB   256
#define ASTR  1040        // A row stride bytes (1024 data + 16 pad, conflict-free)
#define MARGIN 0.02f
#define MAXC  16

#define SM_A      0        // 64*1040      = 66560
#define SM_B      66560    // 2*16384      -> 99328 (swizzled, no pad)
#define SM_CSQ    99328    // 4096         -> 103424
#define SM_RSQ    103424   // 256          -> 103680
#define SM_RUNMIN 103680   // 256          -> 103936
#define SM_CCNT   103936   // 256          -> 104192
#define SM_CLIST  104192   // 64*16*4=4096 -> 108288 (PART aliases first 1KB)
#define SM_ROWKEY 108288   // 512          -> 108800
#define SM_TOTAL  108800

__device__ float g_csq[LLEV * KCB];
__device__ float g_res[(size_t)NROWS * DDIM];
__device__ __align__(16) __nv_bfloat16 g_cb16[(size_t)LLEV * KCB * DDIM];

__device__ __forceinline__ uint32_t smem_u32(const void* p) {
    uint32_t a;
    asm("{ .reg .u64 t; cvta.to.shared.u64 t, %1; cvt.u32.u64 %0, t; }" : "=r"(a) : "l"(p));
    return a;
}
__device__ __forceinline__ void cpa16(uint32_t dst, const void* src) {
    asm volatile("cp.async.cg.shared.global [%0], [%1], 16;" :: "r"(dst), "l"(src));
}
__device__ __forceinline__ void cpa_commit() {
    asm volatile("cp.async.commit_group;" ::: "memory");
}
__device__ __forceinline__ void ldm_x4(uint32_t addr, uint32_t* r) {
    asm volatile("ldmatrix.sync.aligned.m8n8.x4.shared.b16 {%0,%1,%2,%3}, [%4];"
                 : "=r"(r[0]), "=r"(r[1]), "=r"(r[2]), "=r"(r[3]) : "r"(addr));
}

#define MMA16816(c, a0, a1, a2, a3, b0, b1)                                     \
    asm volatile(                                                               \
        "mma.sync.aligned.m16n8k16.row.col.f32.bf16.bf16.f32 "                  \
        "{%0,%1,%2,%3}, {%4,%5,%6,%7}, {%8,%9}, {%0,%1,%2,%3};"                 \
        : "+f"((c)[0]), "+f"((c)[1]), "+f"((c)[2]), "+f"((c)[3])                \
        : "r"(a0), "r"(a1), "r"(a2), "r"(a3), "r"(b0), "r"(b1))

__device__ __forceinline__ float dot512(const float* cbrow, int lane,
                                        float4 rv0, float4 rv1, float4 rv2, float4 rv3) {
    const float4* cp = (const float4*)cbrow + lane * 4;
    float4 c0 = cp[0], c1 = cp[1], c2 = cp[2], c3 = cp[3];
    float s = 0.f;
    s = fmaf(rv0.x, c0.x, s); s = fmaf(rv0.y, c0.y, s);
    s = fmaf(rv0.z, c0.z, s); s = fmaf(rv0.w, c0.w, s);
    s = fmaf(rv1.x, c1.x, s); s = fmaf(rv1.y, c1.y, s);
    s = fmaf(rv1.z, c1.z, s); s = fmaf(rv1.w, c1.w, s);
    s = fmaf(rv2.x, c2.x, s); s = fmaf(rv2.y, c2.y, s);
    s = fmaf(rv2.z, c2.z, s); s = fmaf(rv2.w, c2.w, s);
    s = fmaf(rv3.x, c3.x, s); s = fmaf(rv3.y, c3.y, s);
    s = fmaf(rv3.z, c3.z, s); s = fmaf(rv3.w, c3.w, s);
    #pragma unroll
    for (int o = 16; o; o >>= 1) s += __shfl_xor_sync(0xffffffffu, s, o);
    return s;
}

// ---------------------------------------------------------------------------
// prep: exact fp32 csq (R1 order) + bf16-rounded codebook copy
// ---------------------------------------------------------------------------
__global__ void prep_kernel(const float* __restrict__ cb) {
    int warp = (blockIdx.x * blockDim.x + threadIdx.x) >> 5;
    int lane = threadIdx.x & 31;
    if (warp >= LLEV * KCB) return;
    const float4* p = (const float4*)(cb + (size_t)warp * DDIM);
    __nv_bfloat162* o = (__nv_bfloat162*)(g_cb16 + (size_t)warp * DDIM);
    float s = 0.f;
    #pragma unroll
    for (int i = lane; i < DDIM / 4; i += 32) {
        float4 v = p[i];
        s = fmaf(v.x, v.x, s);
        s = fmaf(v.y, v.y, s);
        s = fmaf(v.z, v.z, s);
        s = fmaf(v.w, v.w, s);
        o[2 * i]     = __floats2bfloat162_rn(v.x, v.y);
        o[2 * i + 1] = __floats2bfloat162_rn(v.z, v.w);
    }
    #pragma unroll
    for (int q = 16; q; q >>= 1) s += __shfl_down_sync(0xffffffffu, s, q);
    if (lane == 0) g_csq[warp] = s;
}

// ---------------------------------------------------------------------------
// B tile fill: 256 codes x 32 d (64 bytes), XOR-swizzled 16B segments
// ---------------------------------------------------------------------------
__device__ __forceinline__ void bload(uint32_t sma, const __nv_bfloat16* cb16l,
                                      int buf, int cq, int dc, int t) {
    uint32_t dst0 = sma + SM_B + buf * 16384;
    const char* src0 = (const char*)cb16l + (size_t)cq * 256 * 1024 + dc * 64;
    #pragma unroll
    for (int i = 0; i < 4; ++i) {
        int e = t + i * TPB;            // 0..1023
        int code = e >> 2, seg = e & 3;
        uint32_t off = (uint32_t)(code * 64) + (uint32_t)((seg ^ ((code >> 1) & 3)) << 4);
        cpa16(dst0 + off, src0 + (size_t)code * 1024 + seg * 16);
    }
}

// ---------------------------------------------------------------------------
__global__ void __launch_bounds__(TPB, 2)
rq_kernel(const float* __restrict__ inp, const float* __restrict__ cb,
          float* __restrict__ outq, float* __restrict__ outc, int write_codes)
{
    extern __shared__ char smb[];
    float* csq_s = (float*)(smb + SM_CSQ);
    float* rsq_s = (float*)(smb + SM_RSQ);
    float* part  = (float*)(smb + SM_CLIST);   // aliased: dead before clist is used
    uint32_t* runmin = (uint32_t*)(smb + SM_RUNMIN);
    uint32_t* ccnt   = (uint32_t*)(smb + SM_CCNT);
    int* clist       = (int*)(smb + SM_CLIST);
    unsigned long long* rowkey = (unsigned long long*)(smb + SM_ROWKEY);

    const int t = threadIdx.x, lane = t & 31, wid = t >> 5;
    const int gid = lane >> 2, tig = lane & 3;
    const int wrow = wid & 1, wcol = wid >> 1;
    const int n0 = blockIdx.x * ROWS;
    const uint32_t sma = smem_u32(smb);
    const int l16 = lane & 15, lhi4 = lane >> 4;

    for (int l = 0; l < LLEV; ++l) {
        const float* rptr = (l ? g_res : inp) + (size_t)n0 * DDIM;
        const float* cbl = cb + (size_t)l * KCB * DDIM;
        const __nv_bfloat16* cb16l = g_cb16 + (size_t)l * KCB * DDIM;

        for (int i = t; i < KCB; i += TPB) csq_s[i] = g_csq[l * KCB + i];
        if (t < ROWS) { runmin[t] = 0x7f800000u; ccnt[t] = 0u; }

        if (l == 0) {
            // level 0 only: convert input -> bf16 A smem; exact rsq partials
            int row = t >> 2, seg = t & 3;
            const float4* rp = (const float4*)(rptr + (size_t)row * DDIM + seg * 128);
            char* ap = smb + SM_A + row * ASTR + seg * 256;
            float s = 0.f;
            #pragma unroll
            for (int m = 0; m < 16; ++m) {
                float4 v0 = rp[2 * m], v1 = rp[2 * m + 1];
                s = fmaf(v0.x, v0.x, s); s = fmaf(v0.y, v0.y, s);
                s = fmaf(v0.z, v0.z, s); s = fmaf(v0.w, v0.w, s);
                s = fmaf(v1.x, v1.x, s); s = fmaf(v1.y, v1.y, s);
                s = fmaf(v1.z, v1.z, s); s = fmaf(v1.w, v1.w, s);
                __nv_bfloat162 b0 = __floats2bfloat162_rn(v0.x, v0.y);
                __nv_bfloat162 b1 = __floats2bfloat162_rn(v0.z, v0.w);
                __nv_bfloat162 b2 = __floats2bfloat162_rn(v1.x, v1.y);
                __nv_bfloat162 b3 = __floats2bfloat162_rn(v1.z, v1.w);
                uint4 u;
                u.x = *(uint32_t*)&b0; u.y = *(uint32_t*)&b1;
                u.z = *(uint32_t*)&b2; u.w = *(uint32_t*)&b3;
                *(uint4*)(ap + m * 16) = u;
            }
            part[seg * ROWS + row] = s;
            __syncthreads();
            if (t < ROWS)
                rsq_s[t] = ((part[t] + part[ROWS + t]) + part[2 * ROWS + t])
                           + part[3 * ROWS + t];
        }
        // (l>0: A smem + rsq_s were produced by the previous level's update)
        __syncthreads();

        // ---- phase 1: approximate GEMM (exact R6 schedule) + margin collection ----
        for (int cq = 0; cq < 4; ++cq) {
            float acc[2][8][4];
            #pragma unroll
            for (int i = 0; i < 2; ++i)
                #pragma unroll
                for (int j = 0; j < 8; ++j)
                    #pragma unroll
                    for (int k = 0; k < 4; ++k) acc[i][j][k] = 0.f;

            bload(sma, cb16l, 0, cq, 0, t); cpa_commit();
            bload(sma, cb16l, 1, cq, 1, t); cpa_commit();

            const uint32_t aaddr0 = sma + SM_A + (wrow * 32 + l16) * ASTR + (lhi4 << 4);
            for (int dc = 0; dc < 16; ++dc) {
                asm volatile("cp.async.wait_group 1;" ::: "memory");
                __syncthreads();
                const uint32_t bbase = sma + SM_B + (dc & 1) * 16384;
                #pragma unroll
                for (int ks = 0; ks < 2; ++ks) {
                    uint32_t a0[4], a1[4];
                    ldm_x4(aaddr0 + dc * 64 + ks * 32, a0);
                    ldm_x4(aaddr0 + 16 * ASTR + dc * 64 + ks * 32, a1);
                    const int bseg = ks * 2 + lhi4;
                    #pragma unroll
                    for (int j2 = 0; j2 < 4; ++j2) {
                        int brow = wcol * 64 + j2 * 16 + l16;
                        uint32_t baddr = bbase + brow * 64
                                         + ((bseg ^ ((brow >> 1) & 3)) << 4);
                        uint32_t b[4];
                        ldm_x4(baddr, b);
                        MMA16816(acc[0][2 * j2],     a0[0], a0[1], a0[2], a0[3], b[0], b[2]);
                        MMA16816(acc[0][2 * j2 + 1], a0[0], a0[1], a0[2], a0[3], b[1], b[3]);
                        MMA16816(acc[1][2 * j2],     a1[0], a1[1], a1[2], a1[3], b[0], b[2]);
                        MMA16816(acc[1][2 * j2 + 1], a1[0], a1[1], a1[2], a1[3], b[1], b[3]);
                    }
                }
                __syncthreads();
                if (dc + 2 < 16) bload(sma, cb16l, dc & 1, cq, dc + 2, t);
                cpa_commit();
            }

            // scores in place of acc; update running row minima
            const int cqbase = cq * 256;
            float rsqv[2][2], smin[2][2];
            #pragma unroll
            for (int i = 0; i < 2; ++i)
                #pragma unroll
                for (int h = 0; h < 2; ++h) {
                    rsqv[i][h] = rsq_s[wrow * 32 + i * 16 + gid + h * 8];
                    smin[i][h] = __int_as_float(0x7f800000);
                }
            #pragma unroll
            for (int i = 0; i < 2; ++i)
                #pragma unroll
                for (int j = 0; j < 8; ++j) {
                    int code0 = cqbase + wcol * 64 + j * 8 + tig * 2;
                    float cq0 = csq_s[code0], cq1 = csq_s[code0 + 1];
                    float s0 = (rsqv[i][0] + cq0) - 2.0f * acc[i][j][0];
                    float s1 = (rsqv[i][0] + cq1) - 2.0f * acc[i][j][1];
                    float s2 = (rsqv[i][1] + cq0) - 2.0f * acc[i][j][2];
                    float s3 = (rsqv[i][1] + cq1) - 2.0f * acc[i][j][3];
                    acc[i][j][0] = s0; acc[i][j][1] = s1;
                    acc[i][j][2] = s2; acc[i][j][3] = s3;
                    smin[i][0] = fminf(smin[i][0], fminf(s0, s1));
                    smin[i][1] = fminf(smin[i][1], fminf(s2, s3));
                }
            #pragma unroll
            for (int i = 0; i < 2; ++i)
                #pragma unroll
                for (int h = 0; h < 2; ++h)
                    atomicMin(&runmin[wrow * 32 + i * 16 + gid + h * 8],
                              __float_as_uint(smin[i][h]));
            __syncthreads();   // collect must see block-wide running min
            // collect candidates within margin of running min
            #pragma unroll
            for (int i = 0; i < 2; ++i) {
                float thr0 = __uint_as_float(runmin[wrow * 32 + i * 16 + gid]) + MARGIN;
                float thr1 = __uint_as_float(runmin[wrow * 32 + i * 16 + gid + 8]) + MARGIN;
                int row0 = wrow * 32 + i * 16 + gid, row1 = row0 + 8;
                #pragma unroll
                for (int j = 0; j < 8; ++j) {
                    int code0 = cqbase + wcol * 64 + j * 8 + tig * 2;
                    if (acc[i][j][0] < thr0) {
                        uint32_t sl = atomicAdd(&ccnt[row0], 1u);
                        if (sl < MAXC) clist[row0 * MAXC + sl] = code0;
                    }
                    if (acc[i][j][1] < thr0) {
                        uint32_t sl = atomicAdd(&ccnt[row0], 1u);
                        if (sl < MAXC) clist[row0 * MAXC + sl] = code0 + 1;
                    }
                    if (acc[i][j][2] < thr1) {
                        uint32_t sl = atomicAdd(&ccnt[row1], 1u);
                        if (sl < MAXC) clist[row1 * MAXC + sl] = code0;
                    }
                    if (acc[i][j][3] < thr1) {
                        uint32_t sl = atomicAdd(&ccnt[row1], 1u);
                        if (sl < MAXC) clist[row1 * MAXC + sl] = code0 + 1;
                    }
                }
            }
            // trailing barrier removed (R15): nothing reads ccnt/clist until
            // phase 2, which is preceded by its own __syncthreads.
        }
        __syncthreads();   // clist/ccnt visible to phase 2

        // ---- phase 2: cnt==1 shortcut; else exact rescore / full scan ----
        for (int r8 = 0; r8 < 8; ++r8) {
            int row = wid * 8 + r8;
            int cnt = (int)ccnt[row];
            if (cnt == 1) {
                // sole within-margin candidate IS the argmin (min always collected)
                if (lane == 0)
                    rowkey[row] = (unsigned long long)(unsigned)clist[row * MAXC];
                continue;
            }
            const float4* rp = (const float4*)(rptr + (size_t)row * DDIM) + lane * 4;
            float4 rv0 = rp[0], rv1 = rp[1], rv2 = rp[2], rv3 = rp[3];
            float rsqv = rsq_s[row];
            unsigned long long best = ~0ull;
            if (cnt <= MAXC) {
                for (int q = 0; q < cnt; ++q) {
                    int code = clist[row * MAXC + q];
                    float s = dot512(cbl + (size_t)code * DDIM, lane, rv0, rv1, rv2, rv3);
                    float d = (rsqv + csq_s[code]) - 2.0f * s;
                    unsigned long long key =
                        ((unsigned long long)__float_as_uint(d) << 32) | (unsigned)code;
                    if (key < best) best = key;
                }
            } else {
                // guaranteed-correct slow path: scan all codes exactly
                for (int code = 0; code < KCB; ++code) {
                    float s = dot512(cbl + (size_t)code * DDIM, lane, rv0, rv1, rv2, rv3);
                    float d = (rsqv + csq_s[code]) - 2.0f * s;
                    unsigned long long key =
                        ((unsigned long long)__float_as_uint(d) << 32) | (unsigned)code;
                    if (key < best) best = key;
                }
            }
            if (lane == 0) rowkey[row] = best;
        }
        __syncthreads();

        // ---- fused update, warp-per-row (coalesced, one reduce per row) ----
        if (l < LLEV - 1) {
            // v = r - e (exact fp32) -> g_res, bf16 A smem; rsq_s written by lane0
            for (int r8 = 0; r8 < 8; ++r8) {
                int row = wid * 8 + r8;
                unsigned idx = (unsigned)(rowkey[row] & 0xffffffffu);
                const float4* ep = (const float4*)(cbl + (size_t)idx * DDIM);
                const float4* rp = (const float4*)(rptr + (size_t)row * DDIM);
                float4* gp = (float4*)(g_res + (size_t)(n0 + row) * DDIM);
                char* ap = smb + SM_A + row * ASTR;
                float s = 0.f;
                #pragma unroll
                for (int p = 0; p < 4; ++p) {
                    int dq = lane + 32 * p;
                    float4 e = ep[dq];
                    float4 v = rp[dq];
                    v.x -= e.x; v.y -= e.y; v.z -= e.z; v.w -= e.w;
                    gp[dq] = v;
                    __nv_bfloat162 b0 = __floats2bfloat162_rn(v.x, v.y);
                    __nv_bfloat162 b1 = __floats2bfloat162_rn(v.z, v.w);
                    uint2 u;
                    u.x = *(uint32_t*)&b0;
                    u.y = *(uint32_t*)&b1;
                    *(uint2*)(ap + dq * 8) = u;
                    s = fmaf(v.x, v.x, s); s = fmaf(v.y, v.y, s);
                    s = fmaf(v.z, v.z, s); s = fmaf(v.w, v.w, s);
                }
                #pragma unroll
                for (int o = 16; o; o >>= 1) s += __shfl_xor_sync(0xffffffffu, s, o);
                if (lane == 0) rsq_s[row] = s;
            }
        } else {
            // last level: quant = inputs - residual_final, written once
            const float* inb = inp + (size_t)n0 * DDIM;
            #pragma unroll 4
            for (int k = 0; k < 32; ++k) {
                int i = t + k * TPB;
                int row = i >> 7, dq = i & 127;
                unsigned idx = (unsigned)(rowkey[row] & 0xffffffffu);
                float4 e = ((const float4*)(cbl + (size_t)idx * DDIM))[dq];
                float4 r = ((const float4*)(rptr + (size_t)row * DDIM))[dq];
                r.x -= e.x; r.y -= e.y; r.z -= e.z; r.w -= e.w;
                float4 in = ((const float4*)(inb + (size_t)row * DDIM))[dq];
                float4 q;
                q.x = in.x - r.x; q.y = in.y - r.y;
                q.z = in.z - r.z; q.w = in.w - r.w;
                ((float4*)(outq + (size_t)(n0 + row) * DDIM))[dq] = q;
            }
        }
        if (write_codes && t < ROWS) {
            unsigned idx = (unsigned)(rowkey[t] & 0xffffffffu);
            outc[(size_t)(n0 + t) * LLEV + l] = (float)idx;
        }
        __syncthreads();   // A smem + rsq_s ready for next level
    }
}

// ---------------------------------------------------------------------------
extern "C" void kernel_launch(void* const* d_in, const int* in_sizes, int n_in,
                              void* d_out, int out_size) {
    const float* inp = (const float*)d_in[0];
    const float* cb  = (const float*)d_in[1];
    if (n_in >= 2 && in_sizes[0] == LLEV * KCB * DDIM && in_sizes[1] == NROWS * DDIM) {
        const float* tmp = inp; inp = cb; cb = tmp;
    }
    float* outq = (float*)d_out;
    float* outc = nullptr;
    int write_codes = 0;
    long long quant_elems = (long long)NROWS * DDIM;
    if ((long long)out_size >= quant_elems + (long long)NROWS * LLEV) {
        write_codes = 1;
        outc = outq + quant_elems;
    }

    prep_kernel<<<(LLEV * KCB * 32 + 255) / 256, 256>>>(cb);

    cudaFuncSetAttribute(rq_kernel, cudaFuncAttributeMaxDynamicSharedMemorySize, SM_TOTAL);
    rq_kernel<<<NROWS / ROWS, TPB, SM_TOTAL>>>(inp, cb, outq, outc, write_codes);
}